// round 8
// baseline (speedup 1.0000x reference)
#include <cuda_runtime.h>
#include <math.h>
#include <float.h>

// Problem constants
#define BB 8
#define TT 2048
#define DD 768
#define VQ 64
#define L2B 12
#define HID 1024
#define KK 4096            // codebook size
#define NROWS (BB*TT)      // 16384
#define N_MID 4

// ---------------- device scratch (static, allocation-free) ----------------
__device__ __align__(16) float g_bufA[KK * HID];      // 16MB
__device__ __align__(16) float g_bufB[KK * HID];      // 16MB
__device__ __align__(16) float g_part_sum[32 * HID];
__device__ __align__(16) float g_part_sq[32 * HID];
__device__ __align__(16) float g_scale[HID];
__device__ __align__(16) float g_shift[HID];
__device__ __align__(16) float g_embed[KK * VQ];      // 1MB (L2-resident)
__device__ __align__(16) float g_embsq[KK];
__device__ __align__(16) float g_h[NROWS * VQ];       // 4MB
__device__ int g_code[NROWS];

// =====================================================================
// Layer 0: y0[k,c] = sum_j bits[k,j]*W_in[c,j] + b_in[c]  (+ BN partials)
// grid(32), block(256)
// =====================================================================
__global__ void layer0_kernel(const float* __restrict__ W_in,
                              const float* __restrict__ b_in) {
    __shared__ float Ws[L2B][HID];
    int tid = threadIdx.x;
    for (int i = tid; i < HID * L2B; i += 256) {
        int c = i / L2B, j = i % L2B;
        Ws[j][c] = W_in[i];
    }
    __syncthreads();
    int rt = blockIdx.x;
    for (int cc = 0; cc < 4; cc++) {
        int c = cc * 256 + tid;
        float bb = b_in[c];
        float w[L2B];
#pragma unroll
        for (int j = 0; j < L2B; j++) w[j] = Ws[j][c];
        float s = 0.f, sq = 0.f;
        for (int r = 0; r < 128; r++) {
            int k = rt * 128 + r;
            float y = bb;
#pragma unroll
            for (int j = 0; j < L2B; j++)
                if ((k >> (11 - j)) & 1) y += w[j];
            g_bufA[(size_t)k * HID + c] = y;
            s += y; sq += y * y;
        }
        g_part_sum[rt * HID + c] = s;
        g_part_sq[rt * HID + c] = sq;
    }
}

// =====================================================================
// BN stats: fold 32 deterministic partials -> scale/shift per column.
// =====================================================================
__global__ void stats_kernel(const float* __restrict__ gamma,
                             const float* __restrict__ beta) {
    int c = blockIdx.x * 256 + threadIdx.x;
    float s = 0.f, sq = 0.f;
#pragma unroll
    for (int rt = 0; rt < 32; rt++) {
        s  += g_part_sum[rt * HID + c];
        sq += g_part_sq[rt * HID + c];
    }
    float m = s * (1.0f / 4096.0f);
    float v = sq * (1.0f / 4096.0f) - m * m;
    float sc = gamma[c] * rsqrtf(v + 1e-5f);
    g_scale[c] = sc;
    g_shift[c] = beta[c] - m * sc;
}

// =====================================================================
// BN + ReLU elementwise (in place).
// =====================================================================
__global__ void bn_relu_kernel(int buf) {
    float* X = buf ? g_bufB : g_bufA;
    int i = blockIdx.x * 256 + threadIdx.x;
    int c4 = (i & 255) * 4;
    float4 v  = ((float4*)X)[i];
    float4 sc = *(const float4*)&g_scale[c4];
    float4 sh = *(const float4*)&g_shift[c4];
    v.x = fmaxf(0.f, fmaf(v.x, sc.x, sh.x));
    v.y = fmaxf(0.f, fmaf(v.y, sc.y, sh.y));
    v.z = fmaxf(0.f, fmaf(v.z, sc.z, sh.z));
    v.w = fmaxf(0.f, fmaf(v.w, sc.w, sh.w));
    ((float4*)X)[i] = v;
}

// =====================================================================
// Mid-layer SGEMM: Y[4096,1024] = A[4096,1024] * W[1024,1024]^T + bias
// + deterministic BN partials.
// BM=128, BN=64, BK=16, 8x4 microtile, 3 CTAs/SM target.
// grid(16, 32), block(256).  sel: 0 -> A=bufA,Y=bufB ; 1 -> A=bufB,Y=bufA
// =====================================================================
__global__ __launch_bounds__(256, 3) void gemm_mid(int sel,
                                                   const float* __restrict__ W,
                                                   const float* __restrict__ bias) {
    const float* __restrict__ A = sel ? g_bufB : g_bufA;
    float* __restrict__ Y = sel ? g_bufA : g_bufB;
    __shared__ __align__(16) float As[16][132];
    __shared__ __align__(16) float Bs[16][68];
    const int tid = threadIdx.x;
    const int ct = blockIdx.x, rt = blockIdx.y;
    const int tx = tid & 15, ty = tid >> 4;
    const int lr0 = tid >> 2;            // 0..63
    const int lc4 = (tid & 3) * 4;       // k offset 0,4,8,12
    const float* Ap = A + ((size_t)(rt * 128) + lr0) * 1024 + lc4;
    const float* Bp = W + ((size_t)(ct * 64) + lr0) * 1024 + lc4;

    float4 a0 = *(const float4*)(Ap);
    float4 a1 = *(const float4*)(Ap + (size_t)64 * 1024);
    float4 b0 = *(const float4*)(Bp);

    float acc[8][4];
#pragma unroll
    for (int i = 0; i < 8; i++)
#pragma unroll
        for (int j = 0; j < 4; j++) acc[i][j] = 0.f;

    for (int k0 = 0; k0 < 1024; k0 += 16) {
        As[lc4 + 0][lr0] = a0.x; As[lc4 + 1][lr0] = a0.y;
        As[lc4 + 2][lr0] = a0.z; As[lc4 + 3][lr0] = a0.w;
        As[lc4 + 0][64 + lr0] = a1.x; As[lc4 + 1][64 + lr0] = a1.y;
        As[lc4 + 2][64 + lr0] = a1.z; As[lc4 + 3][64 + lr0] = a1.w;
        Bs[lc4 + 0][lr0] = b0.x; Bs[lc4 + 1][lr0] = b0.y;
        Bs[lc4 + 2][lr0] = b0.z; Bs[lc4 + 3][lr0] = b0.w;
        __syncthreads();
        if (k0 + 16 < 1024) {
            a0 = *(const float4*)(Ap + k0 + 16);
            a1 = *(const float4*)(Ap + k0 + 16 + (size_t)64 * 1024);
            b0 = *(const float4*)(Bp + k0 + 16);
        }
#pragma unroll
        for (int k = 0; k < 16; k++) {
            float4 av0 = *(const float4*)&As[k][ty * 8];
            float4 av1 = *(const float4*)&As[k][ty * 8 + 4];
            float4 bv  = *(const float4*)&Bs[k][tx * 4];
            float ar[8] = {av0.x, av0.y, av0.z, av0.w, av1.x, av1.y, av1.z, av1.w};
            float br[4] = {bv.x, bv.y, bv.z, bv.w};
#pragma unroll
            for (int i = 0; i < 8; i++)
#pragma unroll
                for (int j = 0; j < 4; j++)
                    acc[i][j] = fmaf(ar[i], br[j], acc[i][j]);
        }
        __syncthreads();
    }

    // epilogue: add bias, write Y, deterministic column partials
    float bj[4];
#pragma unroll
    for (int j = 0; j < 4; j++) bj[j] = bias[ct * 64 + tx * 4 + j];
    float cs[4], cq[4];
#pragma unroll
    for (int j = 0; j < 4; j++) { cs[j] = 0.f; cq[j] = 0.f; }
#pragma unroll
    for (int i = 0; i < 8; i++) {
        float v[4];
#pragma unroll
        for (int j = 0; j < 4; j++) {
            v[j] = acc[i][j] + bj[j];
            cs[j] += v[j];
            cq[j] += v[j] * v[j];
        }
        *(float4*)&Y[((size_t)(rt * 128 + ty * 8 + i)) * 1024 + ct * 64 + tx * 4] =
            make_float4(v[0], v[1], v[2], v[3]);
    }
    float* red = &As[0][0];   // reuse smem: 16 x 64 = 1024 floats
#pragma unroll
    for (int j = 0; j < 4; j++) red[ty * 64 + tx * 4 + j] = cs[j];
    __syncthreads();
    if (tid < 64) {
        float s = 0.f;
#pragma unroll
        for (int t = 0; t < 16; t++) s += red[t * 64 + tid];
        g_part_sum[rt * HID + ct * 64 + tid] = s;
    }
    __syncthreads();
#pragma unroll
    for (int j = 0; j < 4; j++) red[ty * 64 + tx * 4 + j] = cq[j];
    __syncthreads();
    if (tid < 64) {
        float s = 0.f;
#pragma unroll
        for (int t = 0; t < 16; t++) s += red[t * 64 + tid];
        g_part_sq[rt * HID + ct * 64 + tid] = s;
    }
}

// =====================================================================
// Output layer: embed[4096,64] = act(bufA) @ W_out^T + b_out, L2-norm.
// BM=128, BN=64, BK=16, micro 8x4. grid(32), block(256)
// =====================================================================
__global__ __launch_bounds__(256) void gemm_embed(const float* __restrict__ W,
                                                  const float* __restrict__ bias) {
    const float* __restrict__ A = g_bufA;
    __shared__ __align__(16) float As[16][132];
    __shared__ __align__(16) float Bs[16][68];
    __shared__ float rinv[128];
    const int tid = threadIdx.x;
    const int rt = blockIdx.x;
    const int tx = tid & 15, ty = tid >> 4;
    const int lr0 = tid >> 2;
    const int lc4 = (tid & 3) * 4;
    const float* Ap = A + ((size_t)(rt * 128) + lr0) * 1024 + lc4;
    const float* Bp = W + (size_t)lr0 * 1024 + lc4;

    float4 a0 = *(const float4*)(Ap);
    float4 a1 = *(const float4*)(Ap + (size_t)64 * 1024);
    float4 b0 = *(const float4*)(Bp);

    float acc[8][4];
#pragma unroll
    for (int i = 0; i < 8; i++)
#pragma unroll
        for (int j = 0; j < 4; j++) acc[i][j] = 0.f;

    for (int k0 = 0; k0 < 1024; k0 += 16) {
        As[lc4 + 0][lr0] = a0.x; As[lc4 + 1][lr0] = a0.y;
        As[lc4 + 2][lr0] = a0.z; As[lc4 + 3][lr0] = a0.w;
        As[lc4 + 0][64 + lr0] = a1.x; As[lc4 + 1][64 + lr0] = a1.y;
        As[lc4 + 2][64 + lr0] = a1.z; As[lc4 + 3][64 + lr0] = a1.w;
        Bs[lc4 + 0][lr0] = b0.x; Bs[lc4 + 1][lr0] = b0.y;
        Bs[lc4 + 2][lr0] = b0.z; Bs[lc4 + 3][lr0] = b0.w;
        __syncthreads();
        if (k0 + 16 < 1024) {
            a0 = *(const float4*)(Ap + k0 + 16);
            a1 = *(const float4*)(Ap + k0 + 16 + (size_t)64 * 1024);
            b0 = *(const float4*)(Bp + k0 + 16);
        }
#pragma unroll
        for (int k = 0; k < 16; k++) {
            float4 av0 = *(const float4*)&As[k][ty * 8];
            float4 av1 = *(const float4*)&As[k][ty * 8 + 4];
            float4 bv  = *(const float4*)&Bs[k][tx * 4];
            float ar[8] = {av0.x, av0.y, av0.z, av0.w, av1.x, av1.y, av1.z, av1.w};
            float br[4] = {bv.x, bv.y, bv.z, bv.w};
#pragma unroll
            for (int i = 0; i < 8; i++)
#pragma unroll
                for (int j = 0; j < 4; j++)
                    acc[i][j] = fmaf(ar[i], br[j], acc[i][j]);
        }
        __syncthreads();
    }

    float bj[4];
#pragma unroll
    for (int j = 0; j < 4; j++) bj[j] = bias[tx * 4 + j];
    float rsq[8];
#pragma unroll
    for (int i = 0; i < 8; i++) {
        rsq[i] = 0.f;
#pragma unroll
        for (int j = 0; j < 4; j++) {
            acc[i][j] += bj[j];
            rsq[i] += acc[i][j] * acc[i][j];
        }
    }
    float* red = &As[0][0];
#pragma unroll
    for (int i = 0; i < 8; i++) red[(ty * 8 + i) * 16 + tx] = rsq[i];
    __syncthreads();
    if (tid < 128) {
        float s = 0.f;
#pragma unroll
        for (int t = 0; t < 16; t++) s += red[tid * 16 + t];
        float inv = 1.0f / (sqrtf(s) + 1e-6f);
        rinv[tid] = inv;
        g_embsq[rt * 128 + tid] = s * inv * inv;
    }
    __syncthreads();
#pragma unroll
    for (int i = 0; i < 8; i++) {
        float iv = rinv[ty * 8 + i];
        float4 o = make_float4(acc[i][0] * iv, acc[i][1] * iv,
                               acc[i][2] * iv, acc[i][3] * iv);
        *(float4*)&g_embed[(size_t)(rt * 128 + ty * 8 + i) * 64 + tx * 4] = o;
    }
}

// =====================================================================
// Projection: h[b,t,v] = sum_d h_in[b,d,t]*proj_w[v,d] + proj_b[v], L2-norm.
// grid(16, 8), block(256). BM=128(t), BN=64, BK=16, K=768.
// =====================================================================
__global__ __launch_bounds__(256) void proj_kernel(const float* __restrict__ h_in,
                                                   const float* __restrict__ pw,
                                                   const float* __restrict__ pb) {
    __shared__ __align__(16) float As[16][132];
    __shared__ __align__(16) float Bs[16][68];
    __shared__ float rinv[128];
    const int tid = threadIdx.x;
    const int tt = blockIdx.x;
    const int b  = blockIdx.y;
    const int tx = tid & 15, ty = tid >> 4;
    const int kk = tid >> 4;
    const int r8 = (tid & 15) * 8;
    const float* Ap = h_in + ((size_t)b * 768 + kk) * 2048 + tt * 128 + r8;
    const float* Bp = pw + (size_t)(tid >> 2) * 768 + (tid & 3) * 4;

    float4 a0 = *(const float4*)(Ap);
    float4 a1 = *(const float4*)(Ap + 4);
    float4 b0 = *(const float4*)(Bp);
    const int lr0 = tid >> 2, lc4 = (tid & 3) * 4;

    float acc[8][4];
#pragma unroll
    for (int i = 0; i < 8; i++)
#pragma unroll
        for (int j = 0; j < 4; j++) acc[i][j] = 0.f;

    for (int k0 = 0; k0 < 768; k0 += 16) {
        *(float4*)&As[kk][r8]     = a0;
        *(float4*)&As[kk][r8 + 4] = a1;
        Bs[lc4 + 0][lr0] = b0.x; Bs[lc4 + 1][lr0] = b0.y;
        Bs[lc4 + 2][lr0] = b0.z; Bs[lc4 + 3][lr0] = b0.w;
        __syncthreads();
        if (k0 + 16 < 768) {
            a0 = *(const float4*)(Ap + (size_t)(k0 + 16) * 2048);
            a1 = *(const float4*)(Ap + (size_t)(k0 + 16) * 2048 + 4);
            b0 = *(const float4*)(Bp + k0 + 16);
        }
#pragma unroll
        for (int k = 0; k < 16; k++) {
            float4 av0 = *(const float4*)&As[k][ty * 8];
            float4 av1 = *(const float4*)&As[k][ty * 8 + 4];
            float4 bv  = *(const float4*)&Bs[k][tx * 4];
            float ar[8] = {av0.x, av0.y, av0.z, av0.w, av1.x, av1.y, av1.z, av1.w};
            float br[4] = {bv.x, bv.y, bv.z, bv.w};
#pragma unroll
            for (int i = 0; i < 8; i++)
#pragma unroll
                for (int j = 0; j < 4; j++)
                    acc[i][j] = fmaf(ar[i], br[j], acc[i][j]);
        }
        __syncthreads();
    }

    float bj[4];
#pragma unroll
    for (int j = 0; j < 4; j++) bj[j] = pb[tx * 4 + j];
    float rsq[8];
#pragma unroll
    for (int i = 0; i < 8; i++) {
        rsq[i] = 0.f;
#pragma unroll
        for (int j = 0; j < 4; j++) {
            acc[i][j] += bj[j];
            rsq[i] += acc[i][j] * acc[i][j];
        }
    }
    float* red = &As[0][0];
#pragma unroll
    for (int i = 0; i < 8; i++) red[(ty * 8 + i) * 16 + tx] = rsq[i];
    __syncthreads();
    if (tid < 128) {
        float s = 0.f;
#pragma unroll
        for (int t = 0; t < 16; t++) s += red[tid * 16 + t];
        rinv[tid] = 1.0f / (sqrtf(s) + 1e-6f);
    }
    __syncthreads();
#pragma unroll
    for (int i = 0; i < 8; i++) {
        float iv = rinv[ty * 8 + i];
        float4 o = make_float4(acc[i][0] * iv, acc[i][1] * iv,
                               acc[i][2] * iv, acc[i][3] * iv);
        size_t row = (size_t)b * 2048 + tt * 128 + ty * 8 + i;
        *(float4*)&g_h[row * 64 + tx * 4] = o;
    }
}

// =====================================================================
// Distance + argmin.  64 h-rows per block (256 blocks -> 2 CTAs/SM,
// 16 warps/SM), stream 32 tiles of 128 codes.  4x8 microtile.
// d = |e|^2 - 2 h.e ; argmin with lowest-index ties.
// dyn smem = 64*68*4 + 64*132*4 = 51200 B
// =====================================================================
#define DIST_SMEM (64 * 68 * 4 + 64 * 132 * 4)
__global__ __launch_bounds__(256, 2) void dist_kernel() {
    extern __shared__ __align__(16) float sm[];
    float* hs = sm;                 // [64 k][68]  (64 rows + pad)
    float* es = sm + 64 * 68;       // [64 k][132] (128 codes + pad)
    const int tid = threadIdx.x;
    const int tx = tid & 15, ty = tid >> 4;
    const int r0 = blockIdx.x * 64;

    // load 64 h rows: 4096 floats = 1024 float4, 4 per thread
#pragma unroll
    for (int i = 0; i < 4; i++) {
        int f4id = tid + 256 * i;
        int row = f4id >> 4;            // 0..63
        int k4 = (f4id & 15) * 4;
        float4 hv = *(const float4*)&g_h[(size_t)(r0 + row) * 64 + k4];
        hs[(k4 + 0) * 68 + row] = hv.x;
        hs[(k4 + 1) * 68 + row] = hv.y;
        hs[(k4 + 2) * 68 + row] = hv.z;
        hs[(k4 + 3) * 68 + row] = hv.w;
    }
    float bestv[4];
    int besti[4];
#pragma unroll
    for (int i = 0; i < 4; i++) { bestv[i] = FLT_MAX; besti[i] = 0; }
    __syncthreads();

    for (int ctb = 0; ctb < 32; ctb++) {
#pragma unroll
        for (int i = 0; i < 8; i++) {
            int f4id = tid + 256 * i;
            int row = f4id >> 4;        // 0..127 code within tile
            int k4 = (f4id & 15) * 4;
            float4 ev = *(const float4*)&g_embed[(size_t)(ctb * 128 + row) * 64 + k4];
            es[(k4 + 0) * 132 + row] = ev.x;
            es[(k4 + 1) * 132 + row] = ev.y;
            es[(k4 + 2) * 132 + row] = ev.z;
            es[(k4 + 3) * 132 + row] = ev.w;
        }
        __syncthreads();
        float acc[4][8];
#pragma unroll
        for (int i = 0; i < 4; i++)
#pragma unroll
            for (int j = 0; j < 8; j++) acc[i][j] = 0.f;
#pragma unroll 4
        for (int k = 0; k < 64; k++) {
            float4 av  = *(const float4*)&hs[k * 68 + ty * 4];
            float4 bv0 = *(const float4*)&es[k * 132 + tx * 8];
            float4 bv1 = *(const float4*)&es[k * 132 + tx * 8 + 4];
            float ar[4] = {av.x, av.y, av.z, av.w};
            float br[8] = {bv0.x, bv0.y, bv0.z, bv0.w, bv1.x, bv1.y, bv1.z, bv1.w};
#pragma unroll
            for (int i = 0; i < 4; i++)
#pragma unroll
                for (int j = 0; j < 8; j++)
                    acc[i][j] = fmaf(ar[i], br[j], acc[i][j]);
        }
#pragma unroll
        for (int j = 0; j < 8; j++) {
            int c = ctb * 128 + tx * 8 + j;
            float eq = g_embsq[c];
#pragma unroll
            for (int i = 0; i < 4; i++) {
                float d = fmaf(-2.0f, acc[i][j], eq);
                if (d < bestv[i]) { bestv[i] = d; besti[i] = c; }
            }
        }
        __syncthreads();
    }

    // cross-thread per-row reduction with lowest-index tie break
    float* rv = sm;                  // [64][16]
    int* ri = (int*)(sm + 1024);     // [64][16]
#pragma unroll
    for (int i = 0; i < 4; i++) {
        rv[(ty * 4 + i) * 16 + tx] = bestv[i];
        ri[(ty * 4 + i) * 16 + tx] = besti[i];
    }
    __syncthreads();
    if (tid < 64) {
        float bv = rv[tid * 16];
        int bi = ri[tid * 16];
#pragma unroll
        for (int t = 1; t < 16; t++) {
            float v = rv[tid * 16 + t];
            int ix = ri[tid * 16 + t];
            if (v < bv || (v == bv && ix < bi)) { bv = v; bi = ix; }
        }
        g_code[r0 + tid] = bi;
    }
}

// =====================================================================
// Inverse projection. grid(6, 128), block(256). dyn smem 67584 B
// =====================================================================
#define INV_SMEM (2 * 64 * 132 * 4)
__global__ __launch_bounds__(256) void invproj_kernel(const int* __restrict__ attn_mask,
                                                      const float* __restrict__ inv_w,
                                                      const float* __restrict__ inv_b,
                                                      float* __restrict__ out) {
    extern __shared__ __align__(16) float sm2[];
    float* as = sm2;
    float* bs = sm2 + 64 * 132;
    const int tid = threadIdx.x;
    const int ct = blockIdx.x, rb = blockIdx.y;
    const int tx = tid & 15, ty = tid >> 4;
    const int r0 = rb * 128, c0 = ct * 128;

#pragma unroll
    for (int i = 0; i < 8; i++) {
        int f4id = tid + 256 * i;
        int row = f4id >> 4;
        int k4 = (f4id & 15) * 4;
        int r = r0 + row;
        float4 ev = make_float4(0.f, 0.f, 0.f, 0.f);
        if (attn_mask[r] == 1) {
            int cd = g_code[r];
            ev = *(const float4*)&g_embed[(size_t)cd * 64 + k4];
        }
        as[(k4 + 0) * 132 + row] = ev.x;
        as[(k4 + 1) * 132 + row] = ev.y;
        as[(k4 + 2) * 132 + row] = ev.z;
        as[(k4 + 3) * 132 + row] = ev.w;
        float4 wv = *(const float4*)&inv_w[(size_t)(c0 + row) * 64 + k4];
        bs[(k4 + 0) * 132 + row] = wv.x;
        bs[(k4 + 1) * 132 + row] = wv.y;
        bs[(k4 + 2) * 132 + row] = wv.z;
        bs[(k4 + 3) * 132 + row] = wv.w;
    }
    __syncthreads();
    float acc[8][8];
#pragma unroll
    for (int i = 0; i < 8; i++)
#pragma unroll
        for (int j = 0; j < 8; j++) acc[i][j] = 0.f;
#pragma unroll 4
    for (int k = 0; k < 64; k++) {
        float4 av0 = *(const float4*)&as[k * 132 + ty * 8];
        float4 av1 = *(const float4*)&as[k * 132 + ty * 8 + 4];
        float4 bv0 = *(const float4*)&bs[k * 132 + tx * 8];
        float4 bv1 = *(const float4*)&bs[k * 132 + tx * 8 + 4];
        float ar[8] = {av0.x, av0.y, av0.z, av0.w, av1.x, av1.y, av1.z, av1.w};
        float br[8] = {bv0.x, bv0.y, bv0.z, bv0.w, bv1.x, bv1.y, bv1.z, bv1.w};
#pragma unroll
        for (int i = 0; i < 8; i++)
#pragma unroll
            for (int j = 0; j < 8; j++)
                acc[i][j] = fmaf(ar[i], br[j], acc[i][j]);
    }
    float bj[8];
#pragma unroll
    for (int j = 0; j < 8; j++) bj[j] = inv_b[c0 + tx * 8 + j];
#pragma unroll
    for (int i = 0; i < 8; i++) {
        size_t row = (size_t)(r0 + ty * 8 + i);
        float4* op = (float4*)&out[row * 768 + c0 + tx * 8];
        op[0] = make_float4(acc[i][0] + bj[0], acc[i][1] + bj[1],
                            acc[i][2] + bj[2], acc[i][3] + bj[3]);
        op[1] = make_float4(acc[i][4] + bj[4], acc[i][5] + bj[5],
                            acc[i][6] + bj[6], acc[i][7] + bj[7]);
    }
}

// =====================================================================
// vq_code output (as float, masked)
// =====================================================================
__global__ void codes_kernel(const int* __restrict__ attn_mask,
                             float* __restrict__ out_codes) {
    int i = blockIdx.x * 256 + threadIdx.x;
    if (i < NROWS)
        out_codes[i] = (attn_mask[i] == 1) ? (float)g_code[i] : 0.0f;
}

// =====================================================================
extern "C" void kernel_launch(void* const* d_in, const int* in_sizes, int n_in,
                              void* d_out, int out_size) {
    const float* h_in      = (const float*)d_in[0];
    const int*   attn_mask = (const int*)  d_in[1];
    const float* proj_w    = (const float*)d_in[2];
    const float* proj_b    = (const float*)d_in[3];
    const float* inv_w     = (const float*)d_in[4];
    const float* inv_b     = (const float*)d_in[5];
    const float* mlp_w_in  = (const float*)d_in[6];
    const float* mlp_b_in  = (const float*)d_in[7];
    const float* mlp_w_mid = (const float*)d_in[8];
    const float* mlp_b_mid = (const float*)d_in[9];
    const float* mlp_w_out = (const float*)d_in[10];
    const float* mlp_b_out = (const float*)d_in[11];
    const float* bn_gamma  = (const float*)d_in[12];
    const float* bn_beta   = (const float*)d_in[13];
    float* out = (float*)d_out;

    cudaFuncSetAttribute(dist_kernel,    cudaFuncAttributeMaxDynamicSharedMemorySize, DIST_SMEM);
    cudaFuncSetAttribute(invproj_kernel, cudaFuncAttributeMaxDynamicSharedMemorySize, INV_SMEM);

    // ---- codebook MLP ----
    layer0_kernel<<<32, 256>>>(mlp_w_in, mlp_b_in);
    stats_kernel<<<4, 256>>>(bn_gamma, bn_beta);
    bn_relu_kernel<<<4096, 256>>>(0);

    for (int l = 0; l < N_MID; l++) {
        int sel = l & 1;   // l=0 reads bufA, writes bufB; alternates
        gemm_mid<<<dim3(16, 32), 256>>>(sel,
                                        mlp_w_mid + (size_t)l * HID * HID,
                                        mlp_b_mid + (size_t)l * HID);
        stats_kernel<<<4, 256>>>(bn_gamma + (size_t)(l + 1) * HID,
                                 bn_beta  + (size_t)(l + 1) * HID);
        bn_relu_kernel<<<4096, 256>>>(1 - sel);
    }

    // after 4 mid layers the activated buffer is g_bufA
    gemm_embed<<<32, 256>>>(mlp_w_out, mlp_b_out);

    // ---- hidden-state projection + normalize ----
    proj_kernel<<<dim3(16, 8), 256>>>(h_in, proj_w, proj_b);

    // ---- nearest code ----
    dist_kernel<<<256, 256, DIST_SMEM>>>();

    // ---- inverse projection (quantized) + codes ----
    invproj_kernel<<<dim3(6, 128), 256, INV_SMEM>>>(attn_mask, inv_w, inv_b, out);
    codes_kernel<<<64, 256>>>(attn_mask, out + (size_t)NROWS * DD);
}

// round 12
// speedup vs baseline: 1.0078x; 1.0078x over previous
#include <cuda_runtime.h>
#include <math.h>
#include <float.h>

// Problem constants
#define BB 8
#define TT 2048
#define DD 768
#define VQ 64
#define L2B 12
#define HID 1024
#define KK 4096            // codebook size
#define NROWS (BB*TT)      // 16384
#define N_MID 4

// ---------------- device scratch (static, allocation-free) ----------------
__device__ __align__(16) float g_bufA[KK * HID];      // 16MB
__device__ __align__(16) float g_bufB[KK * HID];      // 16MB
__device__ __align__(16) float g_part_sum[64 * HID];  // 64 row-tiles of 64 rows
__device__ __align__(16) float g_part_sq[64 * HID];
__device__ __align__(16) float g_scale[HID];
__device__ __align__(16) float g_shift[HID];
__device__ __align__(16) float g_embed[KK * VQ];      // 1MB (L2-resident)
__device__ __align__(16) float g_embsq[KK];
__device__ __align__(16) float g_h[NROWS * VQ];       // 4MB
__device__ int g_code[NROWS];

// =====================================================================
// Layer 0: y0[k,c] = sum_j bits[k,j]*W_in[c,j] + b_in[c]
// Emits BN partials in 64-row-tile layout (two tiles per block).
// grid(32), block(256)
// =====================================================================
__global__ void layer0_kernel(const float* __restrict__ W_in,
                              const float* __restrict__ b_in) {
    __shared__ float Ws[L2B][HID];
    int tid = threadIdx.x;
    for (int i = tid; i < HID * L2B; i += 256) {
        int c = i / L2B, j = i % L2B;
        Ws[j][c] = W_in[i];
    }
    __syncthreads();
    int rt = blockIdx.x;  // rows rt*128 .. +128
    for (int cc = 0; cc < 4; cc++) {
        int c = cc * 256 + tid;
        float bb = b_in[c];
        float w[L2B];
#pragma unroll
        for (int j = 0; j < L2B; j++) w[j] = Ws[j][c];
        float s0 = 0.f, sq0 = 0.f, s1 = 0.f, sq1 = 0.f;
        for (int r = 0; r < 128; r++) {
            int k = rt * 128 + r;
            float y = bb;
#pragma unroll
            for (int j = 0; j < L2B; j++)
                if ((k >> (11 - j)) & 1) y += w[j];
            g_bufA[(size_t)k * HID + c] = y;
            if (r < 64) { s0 += y; sq0 += y * y; }
            else        { s1 += y; sq1 += y * y; }
        }
        g_part_sum[(2 * rt + 0) * HID + c] = s0;
        g_part_sq [(2 * rt + 0) * HID + c] = sq0;
        g_part_sum[(2 * rt + 1) * HID + c] = s1;
        g_part_sq [(2 * rt + 1) * HID + c] = sq1;
    }
}

// =====================================================================
// BN stats: fold 64 deterministic partials -> scale/shift per column.
// grid(4), block(256)
// =====================================================================
__global__ void stats_kernel(const float* __restrict__ gamma,
                             const float* __restrict__ beta) {
    int c = blockIdx.x * 256 + threadIdx.x;
    float s = 0.f, sq = 0.f;
#pragma unroll
    for (int rt = 0; rt < 64; rt++) {
        s  += g_part_sum[rt * HID + c];
        sq += g_part_sq[rt * HID + c];
    }
    float m = s * (1.0f / 4096.0f);
    float v = sq * (1.0f / 4096.0f) - m * m;
    float sc = gamma[c] * rsqrtf(v + 1e-5f);
    g_scale[c] = sc;
    g_shift[c] = beta[c] - m * sc;
}

// =====================================================================
// BN + ReLU elementwise (in place).  buf: 0->g_bufA, 1->g_bufB
// =====================================================================
__global__ void bn_relu_kernel(int buf) {
    float* X = buf ? g_bufB : g_bufA;
    int i = blockIdx.x * 256 + threadIdx.x;
    int c4 = (i & 255) * 4;
    float4 v  = ((float4*)X)[i];
    float4 sc = *(const float4*)&g_scale[c4];
    float4 sh = *(const float4*)&g_shift[c4];
    v.x = fmaxf(0.f, fmaf(v.x, sc.x, sh.x));
    v.y = fmaxf(0.f, fmaf(v.y, sc.y, sh.y));
    v.z = fmaxf(0.f, fmaf(v.z, sc.z, sh.z));
    v.w = fmaxf(0.f, fmaf(v.w, sc.w, sh.w));
    ((float4*)X)[i] = v;
}

// =====================================================================
// Mid-layer SGEMM: Y[4096,1024] = A * W^T + bias  (+ BN partials)
// BM=BN=64, BK=16, 128 threads, 8x4 microtile, 7 CTAs/SM -> single wave
// over grid(16, 64) = 1024 blocks (1036 resident).
// =====================================================================
__global__ __launch_bounds__(128, 7) void gemm_mid(int sel,
                                                   const float* __restrict__ W,
                                                   const float* __restrict__ bias) {
    const float* __restrict__ A = sel ? g_bufB : g_bufA;
    float* __restrict__ Y = sel ? g_bufA : g_bufB;
    __shared__ __align__(16) float As[16][68];
    __shared__ __align__(16) float Bs[16][68];
    const int tid = threadIdx.x;
    const int ct = blockIdx.x, rt = blockIdx.y;
    const int tx = tid & 15, ty = tid >> 4;   // ty 0..7
    const int lr0 = tid >> 1;                 // 0..63
    const int lc8 = (tid & 1) * 8;            // k offset 0 or 8
    const float* Ap = A + ((size_t)(rt * 64) + lr0) * 1024 + lc8;
    const float* Bp = W + ((size_t)(ct * 64) + lr0) * 1024 + lc8;

    float4 a0 = *(const float4*)(Ap);
    float4 a1 = *(const float4*)(Ap + 4);
    float4 b0 = *(const float4*)(Bp);
    float4 b1 = *(const float4*)(Bp + 4);

    float acc[8][4];
#pragma unroll
    for (int i = 0; i < 8; i++)
#pragma unroll
        for (int j = 0; j < 4; j++) acc[i][j] = 0.f;

    for (int k0 = 0; k0 < 1024; k0 += 16) {
        As[lc8 + 0][lr0] = a0.x; As[lc8 + 1][lr0] = a0.y;
        As[lc8 + 2][lr0] = a0.z; As[lc8 + 3][lr0] = a0.w;
        As[lc8 + 4][lr0] = a1.x; As[lc8 + 5][lr0] = a1.y;
        As[lc8 + 6][lr0] = a1.z; As[lc8 + 7][lr0] = a1.w;
        Bs[lc8 + 0][lr0] = b0.x; Bs[lc8 + 1][lr0] = b0.y;
        Bs[lc8 + 2][lr0] = b0.z; Bs[lc8 + 3][lr0] = b0.w;
        Bs[lc8 + 4][lr0] = b1.x; Bs[lc8 + 5][lr0] = b1.y;
        Bs[lc8 + 6][lr0] = b1.z; Bs[lc8 + 7][lr0] = b1.w;
        __syncthreads();
        if (k0 + 16 < 1024) {
            a0 = *(const float4*)(Ap + k0 + 16);
            a1 = *(const float4*)(Ap + k0 + 20);
            b0 = *(const float4*)(Bp + k0 + 16);
            b1 = *(const float4*)(Bp + k0 + 20);
        }
#pragma unroll
        for (int k = 0; k < 16; k++) {
            float4 av0 = *(const float4*)&As[k][ty * 8];
            float4 av1 = *(const float4*)&As[k][ty * 8 + 4];
            float4 bv  = *(const float4*)&Bs[k][tx * 4];
            float ar[8] = {av0.x, av0.y, av0.z, av0.w, av1.x, av1.y, av1.z, av1.w};
            float br[4] = {bv.x, bv.y, bv.z, bv.w};
#pragma unroll
            for (int i = 0; i < 8; i++)
#pragma unroll
                for (int j = 0; j < 4; j++)
                    acc[i][j] = fmaf(ar[i], br[j], acc[i][j]);
        }
        __syncthreads();
    }

    // epilogue: add bias, write Y, deterministic column partials
    float bj[4];
#pragma unroll
    for (int j = 0; j < 4; j++) bj[j] = bias[ct * 64 + tx * 4 + j];
    float cs[4], cq[4];
#pragma unroll
    for (int j = 0; j < 4; j++) { cs[j] = 0.f; cq[j] = 0.f; }
#pragma unroll
    for (int i = 0; i < 8; i++) {
        float v[4];
#pragma unroll
        for (int j = 0; j < 4; j++) {
            v[j] = acc[i][j] + bj[j];
            cs[j] += v[j];
            cq[j] += v[j] * v[j];
        }
        *(float4*)&Y[((size_t)(rt * 64 + ty * 8 + i)) * 1024 + ct * 64 + tx * 4] =
            make_float4(v[0], v[1], v[2], v[3]);
    }
    float* red = &As[0][0];   // 1088 floats; need 8*64=512
#pragma unroll
    for (int j = 0; j < 4; j++) red[ty * 64 + tx * 4 + j] = cs[j];
    __syncthreads();
    if (tid < 64) {
        float s = 0.f;
#pragma unroll
        for (int t = 0; t < 8; t++) s += red[t * 64 + tid];
        g_part_sum[rt * HID + ct * 64 + tid] = s;
    }
    __syncthreads();
#pragma unroll
    for (int j = 0; j < 4; j++) red[ty * 64 + tx * 4 + j] = cq[j];
    __syncthreads();
    if (tid < 64) {
        float s = 0.f;
#pragma unroll
        for (int t = 0; t < 8; t++) s += red[t * 64 + tid];
        g_part_sq[rt * HID + ct * 64 + tid] = s;
    }
}

// =====================================================================
// Output layer: embed[4096,64] = act(bufA) @ W_out^T + b_out, L2-norm.
// BM=128, BN=64, BK=16, micro 8x4. grid(32), block(256)   (R5 version)
// =====================================================================
__global__ __launch_bounds__(256) void gemm_embed(const float* __restrict__ W,
                                                  const float* __restrict__ bias) {
    const float* __restrict__ A = g_bufA;
    __shared__ __align__(16) float As[16][132];
    __shared__ __align__(16) float Bs[16][68];
    __shared__ float rinv[128];
    const int tid = threadIdx.x;
    const int rt = blockIdx.x;
    const int tx = tid & 15, ty = tid >> 4;
    const int lr0 = tid >> 2;
    const int lc4 = (tid & 3) * 4;
    const float* Ap = A + ((size_t)(rt * 128) + lr0) * 1024 + lc4;
    const float* Bp = W + (size_t)lr0 * 1024 + lc4;

    float4 a0 = *(const float4*)(Ap);
    float4 a1 = *(const float4*)(Ap + (size_t)64 * 1024);
    float4 b0 = *(const float4*)(Bp);

    float acc[8][4];
#pragma unroll
    for (int i = 0; i < 8; i++)
#pragma unroll
        for (int j = 0; j < 4; j++) acc[i][j] = 0.f;

    for (int k0 = 0; k0 < 1024; k0 += 16) {
        As[lc4 + 0][lr0] = a0.x; As[lc4 + 1][lr0] = a0.y;
        As[lc4 + 2][lr0] = a0.z; As[lc4 + 3][lr0] = a0.w;
        As[lc4 + 0][64 + lr0] = a1.x; As[lc4 + 1][64 + lr0] = a1.y;
        As[lc4 + 2][64 + lr0] = a1.z; As[lc4 + 3][64 + lr0] = a1.w;
        Bs[lc4 + 0][lr0] = b0.x; Bs[lc4 + 1][lr0] = b0.y;
        Bs[lc4 + 2][lr0] = b0.z; Bs[lc4 + 3][lr0] = b0.w;
        __syncthreads();
        if (k0 + 16 < 1024) {
            a0 = *(const float4*)(Ap + k0 + 16);
            a1 = *(const float4*)(Ap + k0 + 16 + (size_t)64 * 1024);
            b0 = *(const float4*)(Bp + k0 + 16);
        }
#pragma unroll
        for (int k = 0; k < 16; k++) {
            float4 av0 = *(const float4*)&As[k][ty * 8];
            float4 av1 = *(const float4*)&As[k][ty * 8 + 4];
            float4 bv  = *(const float4*)&Bs[k][tx * 4];
            float ar[8] = {av0.x, av0.y, av0.z, av0.w, av1.x, av1.y, av1.z, av1.w};
            float br[4] = {bv.x, bv.y, bv.z, bv.w};
#pragma unroll
            for (int i = 0; i < 8; i++)
#pragma unroll
                for (int j = 0; j < 4; j++)
                    acc[i][j] = fmaf(ar[i], br[j], acc[i][j]);
        }
        __syncthreads();
    }

    float bj[4];
#pragma unroll
    for (int j = 0; j < 4; j++) bj[j] = bias[tx * 4 + j];
    float rsq[8];
#pragma unroll
    for (int i = 0; i < 8; i++) {
        rsq[i] = 0.f;
#pragma unroll
        for (int j = 0; j < 4; j++) {
            acc[i][j] += bj[j];
            rsq[i] += acc[i][j] * acc[i][j];
        }
    }
    float* red = &As[0][0];
#pragma unroll
    for (int i = 0; i < 8; i++) red[(ty * 8 + i) * 16 + tx] = rsq[i];
    __syncthreads();
    if (tid < 128) {
        float s = 0.f;
#pragma unroll
        for (int t = 0; t < 16; t++) s += red[tid * 16 + t];
        float inv = 1.0f / (sqrtf(s) + 1e-6f);
        rinv[tid] = inv;
        g_embsq[rt * 128 + tid] = s * inv * inv;
    }
    __syncthreads();
#pragma unroll
    for (int i = 0; i < 8; i++) {
        float iv = rinv[ty * 8 + i];
        float4 o = make_float4(acc[i][0] * iv, acc[i][1] * iv,
                               acc[i][2] * iv, acc[i][3] * iv);
        *(float4*)&g_embed[(size_t)(rt * 128 + ty * 8 + i) * 64 + tx * 4] = o;
    }
}

// =====================================================================
// Projection: h[b,t,v] = sum_d h_in[b,d,t]*proj_w[v,d] + proj_b[v], L2-norm.
// grid(16, 8), block(256).  (R5 version)
// =====================================================================
__global__ __launch_bounds__(256) void proj_kernel(const float* __restrict__ h_in,
                                                   const float* __restrict__ pw,
                                                   const float* __restrict__ pb) {
    __shared__ __align__(16) float As[16][132];
    __shared__ __align__(16) float Bs[16][68];
    __shared__ float rinv[128];
    const int tid = threadIdx.x;
    const int tt = blockIdx.x;
    const int b  = blockIdx.y;
    const int tx = tid & 15, ty = tid >> 4;
    const int kk = tid >> 4;
    const int r8 = (tid & 15) * 8;
    const float* Ap = h_in + ((size_t)b * 768 + kk) * 2048 + tt * 128 + r8;
    const float* Bp = pw + (size_t)(tid >> 2) * 768 + (tid & 3) * 4;

    float4 a0 = *(const float4*)(Ap);
    float4 a1 = *(const float4*)(Ap + 4);
    float4 b0 = *(const float4*)(Bp);
    const int lr0 = tid >> 2, lc4 = (tid & 3) * 4;

    float acc[8][4];
#pragma unroll
    for (int i = 0; i < 8; i++)
#pragma unroll
        for (int j = 0; j < 4; j++) acc[i][j] = 0.f;

    for (int k0 = 0; k0 < 768; k0 += 16) {
        *(float4*)&As[kk][r8]     = a0;
        *(float4*)&As[kk][r8 + 4] = a1;
        Bs[lc4 + 0][lr0] = b0.x; Bs[lc4 + 1][lr0] = b0.y;
        Bs[lc4 + 2][lr0] = b0.z; Bs[lc4 + 3][lr0] = b0.w;
        __syncthreads();
        if (k0 + 16 < 768) {
            a0 = *(const float4*)(Ap + (size_t)(k0 + 16) * 2048);
            a1 = *(const float4*)(Ap + (size_t)(k0 + 16) * 2048 + 4);
            b0 = *(const float4*)(Bp + k0 + 16);
        }
#pragma unroll
        for (int k = 0; k < 16; k++) {
            float4 av0 = *(const float4*)&As[k][ty * 8];
            float4 av1 = *(const float4*)&As[k][ty * 8 + 4];
            float4 bv  = *(const float4*)&Bs[k][tx * 4];
            float ar[8] = {av0.x, av0.y, av0.z, av0.w, av1.x, av1.y, av1.z, av1.w};
            float br[4] = {bv.x, bv.y, bv.z, bv.w};
#pragma unroll
            for (int i = 0; i < 8; i++)
#pragma unroll
                for (int j = 0; j < 4; j++)
                    acc[i][j] = fmaf(ar[i], br[j], acc[i][j]);
        }
        __syncthreads();
    }

    float bj[4];
#pragma unroll
    for (int j = 0; j < 4; j++) bj[j] = pb[tx * 4 + j];
    float rsq[8];
#pragma unroll
    for (int i = 0; i < 8; i++) {
        rsq[i] = 0.f;
#pragma unroll
        for (int j = 0; j < 4; j++) {
            acc[i][j] += bj[j];
            rsq[i] += acc[i][j] * acc[i][j];
        }
    }
    float* red = &As[0][0];
#pragma unroll
    for (int i = 0; i < 8; i++) red[(ty * 8 + i) * 16 + tx] = rsq[i];
    __syncthreads();
    if (tid < 128) {
        float s = 0.f;
#pragma unroll
        for (int t = 0; t < 16; t++) s += red[tid * 16 + t];
        rinv[tid] = 1.0f / (sqrtf(s) + 1e-6f);
    }
    __syncthreads();
#pragma unroll
    for (int i = 0; i < 8; i++) {
        float iv = rinv[ty * 8 + i];
        float4 o = make_float4(acc[i][0] * iv, acc[i][1] * iv,
                               acc[i][2] * iv, acc[i][3] * iv);
        size_t row = (size_t)b * 2048 + tt * 128 + ty * 8 + i;
        *(float4*)&g_h[row * 64 + tx * 4] = o;
    }
}

// =====================================================================
// Distance + argmin.  128-thread blocks, 64 h-rows each, 8x8 microtile,
// stream 32 tiles of 128 codes.  grid(256) -> single wave, 4 CTAs/SM.
// dyn smem = 64*68*4 + 64*132*4 = 51200 B
// =====================================================================
#define DIST_SMEM (64 * 68 * 4 + 64 * 132 * 4)
__global__ __launch_bounds__(128) void dist_kernel() {
    extern __shared__ __align__(16) float sm[];
    float* hs = sm;                 // [64 k][68]  (64 rows + pad)
    float* es = sm + 64 * 68;       // [64 k][132] (128 codes + pad)
    const int tid = threadIdx.x;
    const int tx = tid & 15, ty = tid >> 4;   // ty 0..7
    const int r0 = blockIdx.x * 64;

    // load 64 h rows: 4096 floats = 1024 float4, 8 per thread
#pragma unroll
    for (int i = 0; i < 8; i++) {
        int f4id = tid + 128 * i;
        int row = f4id >> 4;            // 0..63
        int k4 = (f4id & 15) * 4;
        float4 hv = *(const float4*)&g_h[(size_t)(r0 + row) * 64 + k4];
        hs[(k4 + 0) * 68 + row] = hv.x;
        hs[(k4 + 1) * 68 + row] = hv.y;
        hs[(k4 + 2) * 68 + row] = hv.z;
        hs[(k4 + 3) * 68 + row] = hv.w;
    }
    float bestv[8];
    int besti[8];
#pragma unroll
    for (int i = 0; i < 8; i++) { bestv[i] = FLT_MAX; besti[i] = 0; }
    __syncthreads();

    for (int ctb = 0; ctb < 32; ctb++) {
        // load 128-code tile: 8192 floats = 2048 float4, 16 per thread
#pragma unroll
        for (int i = 0; i < 16; i++) {
            int f4id = tid + 128 * i;
            int row = f4id >> 4;        // 0..127
            int k4 = (f4id & 15) * 4;
            float4 ev = *(const float4*)&g_embed[(size_t)(ctb * 128 + row) * 64 + k4];
            es[(k4 + 0) * 132 + row] = ev.x;
            es[(k4 + 1) * 132 + row] = ev.y;
            es[(k4 + 2) * 132 + row] = ev.z;
            es[(k4 + 3) * 132 + row] = ev.w;
        }
        __syncthreads();
        float acc[8][8];
#pragma unroll
        for (int i = 0; i < 8; i++)
#pragma unroll
            for (int j = 0; j < 8; j++) acc[i][j] = 0.f;
#pragma unroll 4
        for (int k = 0; k < 64; k++) {
            float4 av0 = *(const float4*)&hs[k * 68 + ty * 8];
            float4 av1 = *(const float4*)&hs[k * 68 + ty * 8 + 4];
            float4 bv0 = *(const float4*)&es[k * 132 + tx * 8];
            float4 bv1 = *(const float4*)&es[k * 132 + tx * 8 + 4];
            float ar[8] = {av0.x, av0.y, av0.z, av0.w, av1.x, av1.y, av1.z, av1.w};
            float br[8] = {bv0.x, bv0.y, bv0.z, bv0.w, bv1.x, bv1.y, bv1.z, bv1.w};
#pragma unroll
            for (int i = 0; i < 8; i++)
#pragma unroll
                for (int j = 0; j < 8; j++)
                    acc[i][j] = fmaf(ar[i], br[j], acc[i][j]);
        }
#pragma unroll
        for (int j = 0; j < 8; j++) {
            int c = ctb * 128 + tx * 8 + j;
            float eq = g_embsq[c];
#pragma unroll
            for (int i = 0; i < 8; i++) {
                float d = fmaf(-2.0f, acc[i][j], eq);
                if (d < bestv[i]) { bestv[i] = d; besti[i] = c; }
            }
        }
        __syncthreads();
    }

    // cross-thread per-row reduction with lowest-index tie break
    float* rv = sm;                  // [64][16]
    int* ri = (int*)(sm + 1024);     // [64][16]
#pragma unroll
    for (int i = 0; i < 8; i++) {
        rv[(ty * 8 + i) * 16 + tx] = bestv[i];
        ri[(ty * 8 + i) * 16 + tx] = besti[i];
    }
    __syncthreads();
    if (tid < 64) {
        float bv = rv[tid * 16];
        int bi = ri[tid * 16];
#pragma unroll
        for (int t = 1; t < 16; t++) {
            float v = rv[tid * 16 + t];
            int ix = ri[tid * 16 + t];
            if (v < bv || (v == bv && ix < bi)) { bv = v; bi = ix; }
        }
        g_code[r0 + tid] = bi;
    }
}

// =====================================================================
// Inverse projection. grid(6, 128), block(256). dyn smem 67584 B (R5)
// =====================================================================
#define INV_SMEM (2 * 64 * 132 * 4)
__global__ __launch_bounds__(256) void invproj_kernel(const int* __restrict__ attn_mask,
                                                      const float* __restrict__ inv_w,
                                                      const float* __restrict__ inv_b,
                                                      float* __restrict__ out) {
    extern __shared__ __align__(16) float sm2[];
    float* as = sm2;
    float* bs = sm2 + 64 * 132;
    const int tid = threadIdx.x;
    const int ct = blockIdx.x, rb = blockIdx.y;
    const int tx = tid & 15, ty = tid >> 4;
    const int r0 = rb * 128, c0 = ct * 128;

#pragma unroll
    for (int i = 0; i < 8; i++) {
        int f4id = tid + 256 * i;
        int row = f4id >> 4;
        int k4 = (f4id & 15) * 4;
        int r = r0 + row;
        float4 ev = make_float4(0.f, 0.f, 0.f, 0.f);
        if (attn_mask[r] == 1) {
            int cd = g_code[r];
            ev = *(const float4*)&g_embed[(size_t)cd * 64 + k4];
        }
        as[(k4 + 0) * 132 + row] = ev.x;
        as[(k4 + 1) * 132 + row] = ev.y;
        as[(k4 + 2) * 132 + row] = ev.z;
        as[(k4 + 3) * 132 + row] = ev.w;
        float4 wv = *(const float4*)&inv_w[(size_t)(c0 + row) * 64 + k4];
        bs[(k4 + 0) * 132 + row] = wv.x;
        bs[(k4 + 1) * 132 + row] = wv.y;
        bs[(k4 + 2) * 132 + row] = wv.z;
        bs[(k4 + 3) * 132 + row] = wv.w;
    }
    __syncthreads();
    float acc[8][8];
#pragma unroll
    for (int i = 0; i < 8; i++)
#pragma unroll
        for (int j = 0; j < 8; j++) acc[i][j] = 0.f;
#pragma unroll 4
    for (int k = 0; k < 64; k++) {
        float4 av0 = *(const float4*)&as[k * 132 + ty * 8];
        float4 av1 = *(const float4*)&as[k * 132 + ty * 8 + 4];
        float4 bv0 = *(const float4*)&bs[k * 132 + tx * 8];
        float4 bv1 = *(const float4*)&bs[k * 132 + tx * 8 + 4];
        float ar[8] = {av0.x, av0.y, av0.z, av0.w, av1.x, av1.y, av1.z, av1.w};
        float br[8] = {bv0.x, bv0.y, bv0.z, bv0.w, bv1.x, bv1.y, bv1.z, bv1.w};
#pragma unroll
        for (int i = 0; i < 8; i++)
#pragma unroll
            for (int j = 0; j < 8; j++)
                acc[i][j] = fmaf(ar[i], br[j], acc[i][j]);
    }
    float bj[8];
#pragma unroll
    for (int j = 0; j < 8; j++) bj[j] = inv_b[c0 + tx * 8 + j];
#pragma unroll
    for (int i = 0; i < 8; i++) {
        size_t row = (size_t)(r0 + ty * 8 + i);
        float4* op = (float4*)&out[row * 768 + c0 + tx * 8];
        op[0] = make_float4(acc[i][0] + bj[0], acc[i][1] + bj[1],
                            acc[i][2] + bj[2], acc[i][3] + bj[3]);
        op[1] = make_float4(acc[i][4] + bj[4], acc[i][5] + bj[5],
                            acc[i][6] + bj[6], acc[i][7] + bj[7]);
    }
}

// =====================================================================
// vq_code output (as float, masked)
// =====================================================================
__global__ void codes_kernel(const int* __restrict__ attn_mask,
                             float* __restrict__ out_codes) {
    int i = blockIdx.x * 256 + threadIdx.x;
    if (i < NROWS)
        out_codes[i] = (attn_mask[i] == 1) ? (float)g_code[i] : 0.0f;
}

// =====================================================================
extern "C" void kernel_launch(void* const* d_in, const int* in_sizes, int n_in,
                              void* d_out, int out_size) {
    const float* h_in      = (const float*)d_in[0];
    const int*   attn_mask = (const int*)  d_in[1];
    const float* proj_w    = (const float*)d_in[2];
    const float* proj_b    = (const float*)d_in[3];
    const float* inv_w     = (const float*)d_in[4];
    const float* inv_b     = (const float*)d_in[5];
    const float* mlp_w_in  = (const float*)d_in[6];
    const float* mlp_b_in  = (const float*)d_in[7];
    const float* mlp_w_mid = (const float*)d_in[8];
    const float* mlp_b_mid = (const float*)d_in[9];
    const float* mlp_w_out = (const float*)d_in[10];
    const float* mlp_b_out = (const float*)d_in[11];
    const float* bn_gamma  = (const float*)d_in[12];
    const float* bn_beta   = (const float*)d_in[13];
    float* out = (float*)d_out;

    cudaFuncSetAttribute(dist_kernel,    cudaFuncAttributeMaxDynamicSharedMemorySize, DIST_SMEM);
    cudaFuncSetAttribute(invproj_kernel, cudaFuncAttributeMaxDynamicSharedMemorySize, INV_SMEM);

    // ---- codebook MLP ----
    layer0_kernel<<<32, 256>>>(mlp_w_in, mlp_b_in);
    stats_kernel<<<4, 256>>>(bn_gamma, bn_beta);
    bn_relu_kernel<<<4096, 256>>>(0);

    for (int l = 0; l < N_MID; l++) {
        int sel = l & 1;   // l=0 reads bufA, writes bufB; alternates
        gemm_mid<<<dim3(16, 64), 128>>>(sel,
                                        mlp_w_mid + (size_t)l * HID * HID,
                                        mlp_b_mid + (size_t)l * HID);
        stats_kernel<<<4, 256>>>(bn_gamma + (size_t)(l + 1) * HID,
                                 bn_beta  + (size_t)(l + 1) * HID);
        bn_relu_kernel<<<4096, 256>>>(1 - sel);
    }

    // after 4 mid layers the activated buffer is g_bufA
    gemm_embed<<<32, 256>>>(mlp_w_out, mlp_b_out);

    // ---- hidden-state projection + normalize ----
    proj_kernel<<<dim3(16, 8), 256>>>(h_in, proj_w, proj_b);

    // ---- nearest code ----
    dist_kernel<<<256, 128, DIST_SMEM>>>();

    // ---- inverse projection (quantized) + codes ----
    invproj_kernel<<<dim3(6, 128), 256, INV_SMEM>>>(attn_mask, inv_w, inv_b, out);
    codes_kernel<<<64, 256>>>(attn_mask, out + (size_t)NROWS * DD);
}

// round 17
// speedup vs baseline: 1.1751x; 1.1660x over previous
#include <cuda_runtime.h>
#include <math.h>
#include <float.h>

// Problem constants
#define BB 8
#define TT 2048
#define DD 768
#define VQ 64
#define L2B 12
#define HID 1024
#define KK 4096            // codebook size
#define NROWS (BB*TT)      // 16384
#define N_MID 4

// ---------------- device scratch (static, allocation-free) ----------------
__device__ __align__(16) float g_bufA[KK * HID];      // 16MB
__device__ __align__(16) float g_bufB[KK * HID];      // 16MB
__device__ __align__(16) float g_part_sum[32 * HID];
__device__ __align__(16) float g_part_sq[32 * HID];
__device__ __align__(16) float g_scale[HID];
__device__ __align__(16) float g_shift[HID];
__device__ __align__(16) float g_embed[KK * VQ];      // 1MB (L2-resident)
__device__ __align__(16) float g_embsq[KK];
__device__ __align__(16) float g_h[NROWS * VQ];       // 4MB
__device__ int g_code[NROWS];

// =====================================================================
// Layer 0: y0[k,c] = sum_j bits[k,j]*W_in[c,j] + b_in[c]  (+ BN partials)
// grid(32), block(256)
// =====================================================================
__global__ void layer0_kernel(const float* __restrict__ W_in,
                              const float* __restrict__ b_in) {
    __shared__ float Ws[L2B][HID];
    int tid = threadIdx.x;
    for (int i = tid; i < HID * L2B; i += 256) {
        int c = i / L2B, j = i % L2B;
        Ws[j][c] = W_in[i];
    }
    __syncthreads();
    int rt = blockIdx.x;
    for (int cc = 0; cc < 4; cc++) {
        int c = cc * 256 + tid;
        float bb = b_in[c];
        float w[L2B];
#pragma unroll
        for (int j = 0; j < L2B; j++) w[j] = Ws[j][c];
        float s = 0.f, sq = 0.f;
        for (int r = 0; r < 128; r++) {
            int k = rt * 128 + r;
            float y = bb;
#pragma unroll
            for (int j = 0; j < L2B; j++)
                if ((k >> (11 - j)) & 1) y += w[j];
            g_bufA[(size_t)k * HID + c] = y;
            s += y; sq += y * y;
        }
        g_part_sum[rt * HID + c] = s;
        g_part_sq[rt * HID + c] = sq;
    }
}

// =====================================================================
// BN stats: fold 32 deterministic partials -> scale/shift per column.
// grid(4), block(256)
// =====================================================================
__global__ void stats_kernel(const float* __restrict__ gamma,
                             const float* __restrict__ beta) {
    int c = blockIdx.x * 256 + threadIdx.x;
    float s = 0.f, sq = 0.f;
#pragma unroll
    for (int rt = 0; rt < 32; rt++) {
        s  += g_part_sum[rt * HID + c];
        sq += g_part_sq[rt * HID + c];
    }
    float m = s * (1.0f / 4096.0f);
    float v = sq * (1.0f / 4096.0f) - m * m;
    float sc = gamma[c] * rsqrtf(v + 1e-5f);
    g_scale[c] = sc;
    g_shift[c] = beta[c] - m * sc;
}

// =====================================================================
// BN + ReLU elementwise (in place).  buf: 0->g_bufA, 1->g_bufB
// =====================================================================
__global__ void bn_relu_kernel(int buf) {
    float* X = buf ? g_bufB : g_bufA;
    int i = blockIdx.x * 256 + threadIdx.x;
    int c4 = (i & 255) * 4;
    float4 v  = ((float4*)X)[i];
    float4 sc = *(const float4*)&g_scale[c4];
    float4 sh = *(const float4*)&g_shift[c4];
    v.x = fmaxf(0.f, fmaf(v.x, sc.x, sh.x));
    v.y = fmaxf(0.f, fmaf(v.y, sc.y, sh.y));
    v.z = fmaxf(0.f, fmaf(v.z, sc.z, sh.z));
    v.w = fmaxf(0.f, fmaf(v.w, sc.w, sh.w));
    ((float4*)X)[i] = v;
}

// =====================================================================
// Mid-layer SGEMM: Y[4096,1024] = A[4096,1024] * W[1024,1024]^T + bias
// + deterministic BN partials.  BM=BN=128, BK=16, 8x8 microtile.
// Lane remap vs R5: warp = 2x4 (wr,wc), within-warp 8x4 (ry,cx) ->
// thread rows wr*64+ry*8.., cols wc*32+cx*8..  (6 smem wavefronts/warp/k
// vs 10).  Per-element math order identical to R5 -> bitwise-same output.
// grid(8, 32), block(256).
// =====================================================================
__global__ __launch_bounds__(256, 2) void gemm_mid(int sel,
                                                   const float* __restrict__ W,
                                                   const float* __restrict__ bias) {
    const float* __restrict__ A = sel ? g_bufB : g_bufA;
    float* __restrict__ Y = sel ? g_bufA : g_bufB;
    __shared__ __align__(16) float As[16][132];
    __shared__ __align__(16) float Bs[16][132];
    const int tid = threadIdx.x;
    const int lane = tid & 31, wid = tid >> 5;
    const int wr = wid >> 2, wc = wid & 3;
    const int ry = lane >> 2, cx = lane & 3;
    const int row0 = wr * 64 + ry * 8;      // this thread's 8 rows
    const int col0 = wc * 32 + cx * 8;      // this thread's 8 cols
    const int ct = blockIdx.x, rt = blockIdx.y;
    const int lr0 = tid >> 2;               // loader: 0..63
    const int lc4 = (tid & 3) * 4;          // loader k offset
    const float* Ap = A + ((size_t)(rt * 128) + lr0) * 1024 + lc4;
    const float* Bp = W + ((size_t)(ct * 128) + lr0) * 1024 + lc4;

    float4 a0 = *(const float4*)(Ap);
    float4 a1 = *(const float4*)(Ap + (size_t)64 * 1024);
    float4 b0 = *(const float4*)(Bp);
    float4 b1 = *(const float4*)(Bp + (size_t)64 * 1024);

    float acc[8][8];
#pragma unroll
    for (int i = 0; i < 8; i++)
#pragma unroll
        for (int j = 0; j < 8; j++) acc[i][j] = 0.f;

    for (int k0 = 0; k0 < 1024; k0 += 16) {
        As[lc4 + 0][lr0] = a0.x; As[lc4 + 1][lr0] = a0.y;
        As[lc4 + 2][lr0] = a0.z; As[lc4 + 3][lr0] = a0.w;
        As[lc4 + 0][64 + lr0] = a1.x; As[lc4 + 1][64 + lr0] = a1.y;
        As[lc4 + 2][64 + lr0] = a1.z; As[lc4 + 3][64 + lr0] = a1.w;
        Bs[lc4 + 0][lr0] = b0.x; Bs[lc4 + 1][lr0] = b0.y;
        Bs[lc4 + 2][lr0] = b0.z; Bs[lc4 + 3][lr0] = b0.w;
        Bs[lc4 + 0][64 + lr0] = b1.x; Bs[lc4 + 1][64 + lr0] = b1.y;
        Bs[lc4 + 2][64 + lr0] = b1.z; Bs[lc4 + 3][64 + lr0] = b1.w;
        __syncthreads();
        if (k0 + 16 < 1024) {
            a0 = *(const float4*)(Ap + k0 + 16);
            a1 = *(const float4*)(Ap + k0 + 16 + (size_t)64 * 1024);
            b0 = *(const float4*)(Bp + k0 + 16);
            b1 = *(const float4*)(Bp + k0 + 16 + (size_t)64 * 1024);
        }
#pragma unroll
        for (int k = 0; k < 16; k++) {
            float4 av0 = *(const float4*)&As[k][row0];
            float4 av1 = *(const float4*)&As[k][row0 + 4];
            float4 bv0 = *(const float4*)&Bs[k][col0];
            float4 bv1 = *(const float4*)&Bs[k][col0 + 4];
            float ar[8] = {av0.x, av0.y, av0.z, av0.w, av1.x, av1.y, av1.z, av1.w};
            float br[8] = {bv0.x, bv0.y, bv0.z, bv0.w, bv1.x, bv1.y, bv1.z, bv1.w};
#pragma unroll
            for (int i = 0; i < 8; i++)
#pragma unroll
                for (int j = 0; j < 8; j++)
                    acc[i][j] = fmaf(ar[i], br[j], acc[i][j]);
        }
        __syncthreads();
    }

    // epilogue: add bias, write Y, accumulate deterministic column partials
    float bj[8];
#pragma unroll
    for (int j = 0; j < 8; j++) bj[j] = bias[ct * 128 + col0 + j];
    float cs[8], cq[8];
#pragma unroll
    for (int j = 0; j < 8; j++) { cs[j] = 0.f; cq[j] = 0.f; }
#pragma unroll
    for (int i = 0; i < 8; i++) {
        float v[8];
#pragma unroll
        for (int j = 0; j < 8; j++) {
            v[j] = acc[i][j] + bj[j];
            cs[j] += v[j];
            cq[j] += v[j] * v[j];
        }
        float4* yp = (float4*)&Y[((size_t)(rt * 128 + row0 + i)) * 1024 + ct * 128 + col0];
        yp[0] = make_float4(v[0], v[1], v[2], v[3]);
        yp[1] = make_float4(v[4], v[5], v[6], v[7]);
    }
    // per column, the 16 contributors are slots s = wr*8+ry covering rows
    // s*8..s*8+7 — same partition and ascending order as R5's ty, so the
    // reduction below is bitwise identical to R5.
    const int slot = wr * 8 + ry;
    float* red = &As[0][0];   // 2112 floats; need 128*16 = 2048
#pragma unroll
    for (int j = 0; j < 8; j++) red[slot * 128 + col0 + j] = cs[j];
    __syncthreads();
    if (tid < 128) {
        float s = 0.f;
#pragma unroll
        for (int t = 0; t < 16; t++) s += red[t * 128 + tid];
        g_part_sum[rt * HID + ct * 128 + tid] = s;
    }
    __syncthreads();
#pragma unroll
    for (int j = 0; j < 8; j++) red[slot * 128 + col0 + j] = cq[j];
    __syncthreads();
    if (tid < 128) {
        float s = 0.f;
#pragma unroll
        for (int t = 0; t < 16; t++) s += red[t * 128 + tid];
        g_part_sq[rt * HID + ct * 128 + tid] = s;
    }
}

// =====================================================================
// Output layer: embed[4096,64] = act(bufA) @ W_out^T + b_out, L2-norm.
// BM=128, BN=64, BK=16, micro 8x4. grid(32), block(256)   (R5 version)
// =====================================================================
__global__ __launch_bounds__(256) void gemm_embed(const float* __restrict__ W,
                                                  const float* __restrict__ bias) {
    const float* __restrict__ A = g_bufA;
    __shared__ __align__(16) float As[16][132];
    __shared__ __align__(16) float Bs[16][68];
    __shared__ float rinv[128];
    const int tid = threadIdx.x;
    const int rt = blockIdx.x;
    const int tx = tid & 15, ty = tid >> 4;
    const int lr0 = tid >> 2;
    const int lc4 = (tid & 3) * 4;
    const float* Ap = A + ((size_t)(rt * 128) + lr0) * 1024 + lc4;
    const float* Bp = W + (size_t)lr0 * 1024 + lc4;

    float4 a0 = *(const float4*)(Ap);
    float4 a1 = *(const float4*)(Ap + (size_t)64 * 1024);
    float4 b0 = *(const float4*)(Bp);

    float acc[8][4];
#pragma unroll
    for (int i = 0; i < 8; i++)
#pragma unroll
        for (int j = 0; j < 4; j++) acc[i][j] = 0.f;

    for (int k0 = 0; k0 < 1024; k0 += 16) {
        As[lc4 + 0][lr0] = a0.x; As[lc4 + 1][lr0] = a0.y;
        As[lc4 + 2][lr0] = a0.z; As[lc4 + 3][lr0] = a0.w;
        As[lc4 + 0][64 + lr0] = a1.x; As[lc4 + 1][64 + lr0] = a1.y;
        As[lc4 + 2][64 + lr0] = a1.z; As[lc4 + 3][64 + lr0] = a1.w;
        Bs[lc4 + 0][lr0] = b0.x; Bs[lc4 + 1][lr0] = b0.y;
        Bs[lc4 + 2][lr0] = b0.z; Bs[lc4 + 3][lr0] = b0.w;
        __syncthreads();
        if (k0 + 16 < 1024) {
            a0 = *(const float4*)(Ap + k0 + 16);
            a1 = *(const float4*)(Ap + k0 + 16 + (size_t)64 * 1024);
            b0 = *(const float4*)(Bp + k0 + 16);
        }
#pragma unroll
        for (int k = 0; k < 16; k++) {
            float4 av0 = *(const float4*)&As[k][ty * 8];
            float4 av1 = *(const float4*)&As[k][ty * 8 + 4];
            float4 bv  = *(const float4*)&Bs[k][tx * 4];
            float ar[8] = {av0.x, av0.y, av0.z, av0.w, av1.x, av1.y, av1.z, av1.w};
            float br[4] = {bv.x, bv.y, bv.z, bv.w};
#pragma unroll
            for (int i = 0; i < 8; i++)
#pragma unroll
                for (int j = 0; j < 4; j++)
                    acc[i][j] = fmaf(ar[i], br[j], acc[i][j]);
        }
        __syncthreads();
    }

    float bj[4];
#pragma unroll
    for (int j = 0; j < 4; j++) bj[j] = bias[tx * 4 + j];
    float rsq[8];
#pragma unroll
    for (int i = 0; i < 8; i++) {
        rsq[i] = 0.f;
#pragma unroll
        for (int j = 0; j < 4; j++) {
            acc[i][j] += bj[j];
            rsq[i] += acc[i][j] * acc[i][j];
        }
    }
    float* red = &As[0][0];
#pragma unroll
    for (int i = 0; i < 8; i++) red[(ty * 8 + i) * 16 + tx] = rsq[i];
    __syncthreads();
    if (tid < 128) {
        float s = 0.f;
#pragma unroll
        for (int t = 0; t < 16; t++) s += red[tid * 16 + t];
        float inv = 1.0f / (sqrtf(s) + 1e-6f);
        rinv[tid] = inv;
        g_embsq[rt * 128 + tid] = s * inv * inv;
    }
    __syncthreads();
#pragma unroll
    for (int i = 0; i < 8; i++) {
        float iv = rinv[ty * 8 + i];
        float4 o = make_float4(acc[i][0] * iv, acc[i][1] * iv,
                               acc[i][2] * iv, acc[i][3] * iv);
        *(float4*)&g_embed[(size_t)(rt * 128 + ty * 8 + i) * 64 + tx * 4] = o;
    }
}

// =====================================================================
// Projection: h[b,t,v] = sum_d h_in[b,d,t]*proj_w[v,d] + proj_b[v], L2-norm.
// grid(16, 8), block(256).  (R5 version)
// =====================================================================
__global__ __launch_bounds__(256) void proj_kernel(const float* __restrict__ h_in,
                                                   const float* __restrict__ pw,
                                                   const float* __restrict__ pb) {
    __shared__ __align__(16) float As[16][132];
    __shared__ __align__(16) float Bs[16][68];
    __shared__ float rinv[128];
    const int tid = threadIdx.x;
    const int tt = blockIdx.x;
    const int b  = blockIdx.y;
    const int tx = tid & 15, ty = tid >> 4;
    const int kk = tid >> 4;
    const int r8 = (tid & 15) * 8;
    const float* Ap = h_in + ((size_t)b * 768 + kk) * 2048 + tt * 128 + r8;
    const float* Bp = pw + (size_t)(tid >> 2) * 768 + (tid & 3) * 4;

    float4 a0 = *(const float4*)(Ap);
    float4 a1 = *(const float4*)(Ap + 4);
    float4 b0 = *(const float4*)(Bp);
    const int lr0 = tid >> 2, lc4 = (tid & 3) * 4;

    float acc[8][4];
#pragma unroll
    for (int i = 0; i < 8; i++)
#pragma unroll
        for (int j = 0; j < 4; j++) acc[i][j] = 0.f;

    for (int k0 = 0; k0 < 768; k0 += 16) {
        *(float4*)&As[kk][r8]     = a0;
        *(float4*)&As[kk][r8 + 4] = a1;
        Bs[lc4 + 0][lr0] = b0.x; Bs[lc4 + 1][lr0] = b0.y;
        Bs[lc4 + 2][lr0] = b0.z; Bs[lc4 + 3][lr0] = b0.w;
        __syncthreads();
        if (k0 + 16 < 768) {
            a0 = *(const float4*)(Ap + (size_t)(k0 + 16) * 2048);
            a1 = *(const float4*)(Ap + (size_t)(k0 + 16) * 2048 + 4);
            b0 = *(const float4*)(Bp + k0 + 16);
        }
#pragma unroll
        for (int k = 0; k < 16; k++) {
            float4 av0 = *(const float4*)&As[k][ty * 8];
            float4 av1 = *(const float4*)&As[k][ty * 8 + 4];
            float4 bv  = *(const float4*)&Bs[k][tx * 4];
            float ar[8] = {av0.x, av0.y, av0.z, av0.w, av1.x, av1.y, av1.z, av1.w};
            float br[4] = {bv.x, bv.y, bv.z, bv.w};
#pragma unroll
            for (int i = 0; i < 8; i++)
#pragma unroll
                for (int j = 0; j < 4; j++)
                    acc[i][j] = fmaf(ar[i], br[j], acc[i][j]);
        }
        __syncthreads();
    }

    float bj[4];
#pragma unroll
    for (int j = 0; j < 4; j++) bj[j] = pb[tx * 4 + j];
    float rsq[8];
#pragma unroll
    for (int i = 0; i < 8; i++) {
        rsq[i] = 0.f;
#pragma unroll
        for (int j = 0; j < 4; j++) {
            acc[i][j] += bj[j];
            rsq[i] += acc[i][j] * acc[i][j];
        }
    }
    float* red = &As[0][0];
#pragma unroll
    for (int i = 0; i < 8; i++) red[(ty * 8 + i) * 16 + tx] = rsq[i];
    __syncthreads();
    if (tid < 128) {
        float s = 0.f;
#pragma unroll
        for (int t = 0; t < 16; t++) s += red[tid * 16 + t];
        rinv[tid] = 1.0f / (sqrtf(s) + 1e-6f);
    }
    __syncthreads();
#pragma unroll
    for (int i = 0; i < 8; i++) {
        float iv = rinv[ty * 8 + i];
        float4 o = make_float4(acc[i][0] * iv, acc[i][1] * iv,
                               acc[i][2] * iv, acc[i][3] * iv);
        size_t row = (size_t)b * 2048 + tt * 128 + ty * 8 + i;
        *(float4*)&g_h[row * 64 + tx * 4] = o;
    }
}

// =====================================================================
// Distance + argmin.  128 h-rows in SMEM, stream 32 tiles of 128 codes.
// Same lane remap as gemm_mid (rows wr*64+ry*8, codes wc*32+cx*8);
// per-element math and tie-break order preserved -> same codes as R5.
// grid(128), block(256), dyn smem 67584 B
// =====================================================================
#define DIST_SMEM (2 * 64 * 132 * 4)
__global__ __launch_bounds__(256) void dist_kernel() {
    extern __shared__ __align__(16) float sm[];
    float* hs = sm;
    float* es = sm + 64 * 132;
    const int tid = threadIdx.x;
    const int lane = tid & 31, wid = tid >> 5;
    const int wr = wid >> 2, wc = wid & 3;
    const int ry = lane >> 2, cx = lane & 3;
    const int row0 = wr * 64 + ry * 8;
    const int col0 = wc * 32 + cx * 8;
    const int r0 = blockIdx.x * 128;

#pragma unroll
    for (int i = 0; i < 8; i++) {
        int f4id = tid + 256 * i;
        int row = f4id >> 4;
        int k4 = (f4id & 15) * 4;
        float4 hv = *(const float4*)&g_h[(size_t)(r0 + row) * 64 + k4];
        hs[(k4 + 0) * 132 + row] = hv.x;
        hs[(k4 + 1) * 132 + row] = hv.y;
        hs[(k4 + 2) * 132 + row] = hv.z;
        hs[(k4 + 3) * 132 + row] = hv.w;
    }
    float bestv[8];
    int besti[8];
#pragma unroll
    for (int i = 0; i < 8; i++) { bestv[i] = FLT_MAX; besti[i] = 0; }
    __syncthreads();

    for (int ctb = 0; ctb < 32; ctb++) {
#pragma unroll
        for (int i = 0; i < 8; i++) {
            int f4id = tid + 256 * i;
            int row = f4id >> 4;
            int k4 = (f4id & 15) * 4;
            float4 ev = *(const float4*)&g_embed[(size_t)(ctb * 128 + row) * 64 + k4];
            es[(k4 + 0) * 132 + row] = ev.x;
            es[(k4 + 1) * 132 + row] = ev.y;
            es[(k4 + 2) * 132 + row] = ev.z;
            es[(k4 + 3) * 132 + row] = ev.w;
        }
        __syncthreads();
        float acc[8][8];
#pragma unroll
        for (int i = 0; i < 8; i++)
#pragma unroll
            for (int j = 0; j < 8; j++) acc[i][j] = 0.f;
#pragma unroll 4
        for (int k = 0; k < 64; k++) {
            float4 av0 = *(const float4*)&hs[k * 132 + row0];
            float4 av1 = *(const float4*)&hs[k * 132 + row0 + 4];
            float4 bv0 = *(const float4*)&es[k * 132 + col0];
            float4 bv1 = *(const float4*)&es[k * 132 + col0 + 4];
            float ar[8] = {av0.x, av0.y, av0.z, av0.w, av1.x, av1.y, av1.z, av1.w};
            float br[8] = {bv0.x, bv0.y, bv0.z, bv0.w, bv1.x, bv1.y, bv1.z, bv1.w};
#pragma unroll
            for (int i = 0; i < 8; i++)
#pragma unroll
                for (int j = 0; j < 8; j++)
                    acc[i][j] = fmaf(ar[i], br[j], acc[i][j]);
        }
#pragma unroll
        for (int j = 0; j < 8; j++) {
            int c = ctb * 128 + col0 + j;
            float eq = g_embsq[c];
#pragma unroll
            for (int i = 0; i < 8; i++) {
                float d = fmaf(-2.0f, acc[i][j], eq);
                if (d < bestv[i]) { bestv[i] = d; besti[i] = c; }
            }
        }
        __syncthreads();
    }

    // cross-thread per-row reduction with lowest-index tie break.
    // slot = wc*4+cx enumerates code ranges in ascending order.
    const int slot = wc * 4 + cx;
    float* rv = sm;                  // [128][16]
    int* ri = (int*)(sm + 2048);     // [128][16]
#pragma unroll
    for (int i = 0; i < 8; i++) {
        rv[(row0 + i) * 16 + slot] = bestv[i];
        ri[(row0 + i) * 16 + slot] = besti[i];
    }
    __syncthreads();
    if (tid < 128) {
        float bv = rv[tid * 16];
        int bi = ri[tid * 16];
#pragma unroll
        for (int t = 1; t < 16; t++) {
            float v = rv[tid * 16 + t];
            int ix = ri[tid * 16 + t];
            if (v < bv || (v == bv && ix < bi)) { bv = v; bi = ix; }
        }
        g_code[r0 + tid] = bi;
    }
}

// =====================================================================
// Inverse projection, same lane remap. grid(6, 128), block(256).
// dyn smem 67584 B
// =====================================================================
#define INV_SMEM (2 * 64 * 132 * 4)
__global__ __launch_bounds__(256) void invproj_kernel(const int* __restrict__ attn_mask,
                                                      const float* __restrict__ inv_w,
                                                      const float* __restrict__ inv_b,
                                                      float* __restrict__ out) {
    extern __shared__ __align__(16) float sm2[];
    float* as = sm2;
    float* bs = sm2 + 64 * 132;
    const int tid = threadIdx.x;
    const int lane = tid & 31, wid = tid >> 5;
    const int wr = wid >> 2, wc = wid & 3;
    const int ry = lane >> 2, cx = lane & 3;
    const int row0 = wr * 64 + ry * 8;
    const int col0 = wc * 32 + cx * 8;
    const int ct = blockIdx.x, rb = blockIdx.y;
    const int r0 = rb * 128, c0 = ct * 128;

#pragma unroll
    for (int i = 0; i < 8; i++) {
        int f4id = tid + 256 * i;
        int row = f4id >> 4;
        int k4 = (f4id & 15) * 4;
        int r = r0 + row;
        float4 ev = make_float4(0.f, 0.f, 0.f, 0.f);
        if (attn_mask[r] == 1) {
            int cd = g_code[r];
            ev = *(const float4*)&g_embed[(size_t)cd * 64 + k4];
        }
        as[(k4 + 0) * 132 + row] = ev.x;
        as[(k4 + 1) * 132 + row] = ev.y;
        as[(k4 + 2) * 132 + row] = ev.z;
        as[(k4 + 3) * 132 + row] = ev.w;
        float4 wv = *(const float4*)&inv_w[(size_t)(c0 + row) * 64 + k4];
        bs[(k4 + 0) * 132 + row] = wv.x;
        bs[(k4 + 1) * 132 + row] = wv.y;
        bs[(k4 + 2) * 132 + row] = wv.z;
        bs[(k4 + 3) * 132 + row] = wv.w;
    }
    __syncthreads();
    float acc[8][8];
#pragma unroll
    for (int i = 0; i < 8; i++)
#pragma unroll
        for (int j = 0; j < 8; j++) acc[i][j] = 0.f;
#pragma unroll 4
    for (int k = 0; k < 64; k++) {
        float4 av0 = *(const float4*)&as[k * 132 + row0];
        float4 av1 = *(const float4*)&as[k * 132 + row0 + 4];
        float4 bv0 = *(const float4*)&bs[k * 132 + col0];
        float4 bv1 = *(const float4*)&bs[k * 132 + col0 + 4];
        float ar[8] = {av0.x, av0.y, av0.z, av0.w, av1.x, av1.y, av1.z, av1.w};
        float br[8] = {bv0.x, bv0.y, bv0.z, bv0.w, bv1.x, bv1.y, bv1.z, bv1.w};
#pragma unroll
        for (int i = 0; i < 8; i++)
#pragma unroll
            for (int j = 0; j < 8; j++)
                acc[i][j] = fmaf(ar[i], br[j], acc[i][j]);
    }
    float bj[8];
#pragma unroll
    for (int j = 0; j < 8; j++) bj[j] = inv_b[c0 + col0 + j];
#pragma unroll
    for (int i = 0; i < 8; i++) {
        size_t row = (size_t)(r0 + row0 + i);
        float4* op = (float4*)&out[row * 768 + c0 + col0];
        op[0] = make_float4(acc[i][0] + bj[0], acc[i][1] + bj[1],
                            acc[i][2] + bj[2], acc[i][3] + bj[3]);
        op[1] = make_float4(acc[i][4] + bj[4], acc[i][5] + bj[5],
                            acc[i][6] + bj[6], acc[i][7] + bj[7]);
    }
}

// =====================================================================
// vq_code output (as float, masked)
// =====================================================================
__global__ void codes_kernel(const int* __restrict__ attn_mask,
                             float* __restrict__ out_codes) {
    int i = blockIdx.x * 256 + threadIdx.x;
    if (i < NROWS)
        out_codes[i] = (attn_mask[i] == 1) ? (float)g_code[i] : 0.0f;
}

// =====================================================================
extern "C" void kernel_launch(void* const* d_in, const int* in_sizes, int n_in,
                              void* d_out, int out_size) {
    const float* h_in      = (const float*)d_in[0];
    const int*   attn_mask = (const int*)  d_in[1];
    const float* proj_w    = (const float*)d_in[2];
    const float* proj_b    = (const float*)d_in[3];
    const float* inv_w     = (const float*)d_in[4];
    const float* inv_b     = (const float*)d_in[5];
    const float* mlp_w_in  = (const float*)d_in[6];
    const float* mlp_b_in  = (const float*)d_in[7];
    const float* mlp_w_mid = (const float*)d_in[8];
    const float* mlp_b_mid = (const float*)d_in[9];
    const float* mlp_w_out = (const float*)d_in[10];
    const float* mlp_b_out = (const float*)d_in[11];
    const float* bn_gamma  = (const float*)d_in[12];
    const float* bn_beta   = (const float*)d_in[13];
    float* out = (float*)d_out;

    cudaFuncSetAttribute(dist_kernel,    cudaFuncAttributeMaxDynamicSharedMemorySize, DIST_SMEM);
    cudaFuncSetAttribute(invproj_kernel, cudaFuncAttributeMaxDynamicSharedMemorySize, INV_SMEM);

    // ---- codebook MLP ----
    layer0_kernel<<<32, 256>>>(mlp_w_in, mlp_b_in);
    stats_kernel<<<4, 256>>>(bn_gamma, bn_beta);
    bn_relu_kernel<<<4096, 256>>>(0);

    for (int l = 0; l < N_MID; l++) {
        int sel = l & 1;   // l=0 reads bufA, writes bufB; alternates
        gemm_mid<<<dim3(8, 32), 256>>>(sel,
                                       mlp_w_mid + (size_t)l * HID * HID,
                                       mlp_b_mid + (size_t)l * HID);
        stats_kernel<<<4, 256>>>(bn_gamma + (size_t)(l + 1) * HID,
                                 bn_beta  + (size_t)(l + 1) * HID);
        bn_relu_kernel<<<4096, 256>>>(1 - sel);
    }

    // after 4 mid layers the activated buffer is g_bufA
    gemm_embed<<<32, 256>>>(mlp_w_out, mlp_b_out);

    // ---- hidden-state projection + normalize ----
    proj_kernel<<<dim3(16, 8), 256>>>(h_in, proj_w, proj_b);

    // ---- nearest code ----
    dist_kernel<<<128, 256, DIST_SMEM>>>();

    // ---- inverse projection (quantized) + codes ----
    invproj_kernel<<<dim3(6, 128), 256, INV_SMEM>>>(attn_mask, inv_w, inv_b, out);
    codes_kernel<<<64, 256>>>(attn_mask, out + (size_t)NROWS * DD);
}